// round 2
// baseline (speedup 1.0000x reference)
#include <cuda_runtime.h>

// DotProductAttention: n=2048 (B=4, W=64, H=8), q=kv=256, d=64
// inputs: [0] queries f32 (2048,256,64)  [1] keys f32 (2048,256,64)
//         [2] values  f32 (2048,256,64)  [3] valid_lens i32 (2048)
//         [4] window_mask f32 (64,256,256)
// output: f32 (2048,256,64)

namespace {

constexpr int QTILE = 64;     // q rows per CTA
constexpr int KVLEN = 256;
constexpr int DIM   = 64;
constexpr int PSTR  = 260;    // padded row stride (floats) for K^T / P buffer (keeps 16B align, breaks worst conflicts)

constexpr int SMEM_FLOATS = 64 * PSTR      // KP: K transposed [d=64][kv=256] then P [q=64][kv=256]
                          + KVLEN * DIM    // V  [256][64]
                          + QTILE * DIM;   // Q  [64][64]
constexpr int SMEM_BYTES = SMEM_FLOATS * 4; // 148480 B

__device__ __forceinline__ float f4get(const float4& v, int k) {
    return k == 0 ? v.x : (k == 1 ? v.y : (k == 2 ? v.z : v.w));
}

__global__ __launch_bounds__(256, 1)
void attn_kernel(const float* __restrict__ Qg, const float* __restrict__ Kg,
                 const float* __restrict__ Vg, const int*   __restrict__ Lg,
                 const float* __restrict__ Wg, float* __restrict__ Og)
{
    extern __shared__ float smem[];
    float* KP = smem;                         // [64][PSTR]  (K^T, later P)
    float* Vs = smem + 64 * PSTR;             // [256][64]
    float* Qs = Vs + KVLEN * DIM;             // [64][64]

    const int b   = blockIdx.y;
    const int q0  = blockIdx.x * QTILE;
    const int w   = (b >> 3) & 63;            // window index: (b / NUM_HEADS) % W
    const int tid = threadIdx.x;
    const int tx  = tid & 15;                 // kv-col group (phase1) / d-col group (phase3)
    const int ty  = tid >> 4;                 // q-row group

    const float4* Q4 = (const float4*)(Qg + ((size_t)b * 256 + q0) * DIM);
    const float4* K4 = (const float4*)(Kg + (size_t)b * KVLEN * DIM);
    const float4* V4 = (const float4*)(Vg + (size_t)b * KVLEN * DIM);

    // ---- loads: Q tile (coalesced), K transposed into KP, V row-major ----
    #pragma unroll
    for (int it = 0; it < 4; ++it) {
        int idx = tid + it * 256;             // 1024 float4 total
        ((float4*)Qs)[idx] = Q4[idx];
    }
    #pragma unroll
    for (int it = 0; it < 16; ++it) {
        int idx = tid + it * 256;             // 4096 float4 total
        int c  = idx >> 4;                    // kv row
        int k4 = (idx & 15) * 4;              // starting k of this float4
        float4 v = K4[idx];
        KP[(k4 + 0) * PSTR + c] = v.x;
        KP[(k4 + 1) * PSTR + c] = v.y;
        KP[(k4 + 2) * PSTR + c] = v.z;
        KP[(k4 + 3) * PSTR + c] = v.w;
    }
    #pragma unroll
    for (int it = 0; it < 16; ++it) {
        int idx = tid + it * 256;
        ((float4*)Vs)[idx] = V4[idx];
    }
    __syncthreads();

    // ---- phase 1: S[r][c] = sum_k Q[r][k] * K[c][k];  r = ty*4+i, c = tx*16+j ----
    float acc[4][16];
    #pragma unroll
    for (int i = 0; i < 4; ++i)
        #pragma unroll
        for (int j = 0; j < 16; ++j) acc[i][j] = 0.0f;

    #pragma unroll 2
    for (int k = 0; k < DIM; k += 4) {
        float4 a[4];
        #pragma unroll
        for (int i = 0; i < 4; ++i)
            a[i] = *(const float4*)(Qs + (ty * 4 + i) * DIM + k);
        #pragma unroll
        for (int kk = 0; kk < 4; ++kk) {
            const float* kr = KP + (k + kk) * PSTR + tx * 16;
            float4 b0 = *(const float4*)(kr + 0);
            float4 b1 = *(const float4*)(kr + 4);
            float4 b2 = *(const float4*)(kr + 8);
            float4 b3 = *(const float4*)(kr + 12);
            float bv[16] = { b0.x, b0.y, b0.z, b0.w,  b1.x, b1.y, b1.z, b1.w,
                             b2.x, b2.y, b2.z, b2.w,  b3.x, b3.y, b3.z, b3.w };
            #pragma unroll
            for (int i = 0; i < 4; ++i) {
                float av = f4get(a[i], kk);
                #pragma unroll
                for (int j = 0; j < 16; ++j)
                    acc[i][j] = fmaf(av, bv[j], acc[i][j]);
            }
        }
    }

    __syncthreads();   // everyone finished reading K^T from KP; safe to overwrite with P

    // ---- phase 2: scale, +window_mask, valid-length mask, softmax, write P ----
    const int   len   = Lg[b];
    const float* wbase = Wg + ((size_t)w * 256 + q0) * 256;

    #pragma unroll
    for (int i = 0; i < 4; ++i) {
        const int r = ty * 4 + i;
        const float* wr = wbase + (size_t)r * 256 + tx * 16;
        float4 w0 = *(const float4*)(wr + 0);
        float4 w1 = *(const float4*)(wr + 4);
        float4 w2 = *(const float4*)(wr + 8);
        float4 w3 = *(const float4*)(wr + 12);
        float wv[16] = { w0.x, w0.y, w0.z, w0.w,  w1.x, w1.y, w1.z, w1.w,
                         w2.x, w2.y, w2.z, w2.w,  w3.x, w3.y, w3.z, w3.w };

        float s[16];
        float m = -3.0e38f;
        #pragma unroll
        for (int j = 0; j < 16; ++j) {
            int c = tx * 16 + j;
            float v = fmaf(acc[i][j], 0.125f, wv[j]);     // /sqrt(64) then +mask
            if (c >= len) v = -1.0e6f;                    // exact -1e6, matches reference
            s[j] = v;
            m = fmaxf(m, v);
        }
        // row reduce across the 16 threads sharing this row (lanes grouped by tx within half-warp)
        m = fmaxf(m, __shfl_xor_sync(0xffffffffu, m, 1));
        m = fmaxf(m, __shfl_xor_sync(0xffffffffu, m, 2));
        m = fmaxf(m, __shfl_xor_sync(0xffffffffu, m, 4));
        m = fmaxf(m, __shfl_xor_sync(0xffffffffu, m, 8));

        float sum = 0.0f;
        #pragma unroll
        for (int j = 0; j < 16; ++j) {
            float e = __expf(s[j] - m);
            s[j] = e;
            sum += e;
        }
        sum += __shfl_xor_sync(0xffffffffu, sum, 1);
        sum += __shfl_xor_sync(0xffffffffu, sum, 2);
        sum += __shfl_xor_sync(0xffffffffu, sum, 4);
        sum += __shfl_xor_sync(0xffffffffu, sum, 8);

        float inv = 1.0f / sum;
        #pragma unroll
        for (int j = 0; j < 16; ++j) s[j] *= inv;

        float* pr = KP + r * PSTR + tx * 16;
        *(float4*)(pr + 0)  = make_float4(s[0],  s[1],  s[2],  s[3]);
        *(float4*)(pr + 4)  = make_float4(s[4],  s[5],  s[6],  s[7]);
        *(float4*)(pr + 8)  = make_float4(s[8],  s[9],  s[10], s[11]);
        *(float4*)(pr + 12) = make_float4(s[12], s[13], s[14], s[15]);
    }
    __syncthreads();

    // ---- phase 3: O[r][dc] = sum_c P[r][c] * V[c][dc];  r = ty*4+i, dc = tx*4+j ----
    float o[4][4];
    #pragma unroll
    for (int i = 0; i < 4; ++i)
        #pragma unroll
        for (int j = 0; j < 4; ++j) o[i][j] = 0.0f;

    #pragma unroll 2
    for (int c = 0; c < KVLEN; c += 4) {
        float4 a[4];
        #pragma unroll
        for (int i = 0; i < 4; ++i)
            a[i] = *(const float4*)(KP + (ty * 4 + i) * PSTR + c);   // broadcast within half-warp
        float4 bm[4];
        #pragma unroll
        for (int t = 0; t < 4; ++t)
            bm[t] = *(const float4*)(Vs + (c + t) * DIM + tx * 4);
        #pragma unroll
        for (int i = 0; i < 4; ++i) {
            #pragma unroll
            for (int t = 0; t < 4; ++t) {
                float av = f4get(a[i], t);
                o[i][0] = fmaf(av, bm[t].x, o[i][0]);
                o[i][1] = fmaf(av, bm[t].y, o[i][1]);
                o[i][2] = fmaf(av, bm[t].z, o[i][2]);
                o[i][3] = fmaf(av, bm[t].w, o[i][3]);
            }
        }
    }

    float* Ob = Og + ((size_t)b * 256 + q0) * DIM;
    #pragma unroll
    for (int i = 0; i < 4; ++i)
        *(float4*)(Ob + (ty * 4 + i) * DIM + tx * 4) = make_float4(o[i][0], o[i][1], o[i][2], o[i][3]);
}

} // namespace

extern "C" void kernel_launch(void* const* d_in, const int* in_sizes, int n_in,
                              void* d_out, int out_size)
{
    const float* Q = (const float*)d_in[0];
    const float* K = (const float*)d_in[1];
    const float* V = (const float*)d_in[2];
    const int*   L = (const int*)  d_in[3];
    const float* W = (const float*)d_in[4];
    float*       O = (float*)d_out;

    const int n = in_sizes[0] / (256 * DIM);   // 2048 batches

    cudaFuncSetAttribute(attn_kernel, cudaFuncAttributeMaxDynamicSharedMemorySize, SMEM_BYTES);

    dim3 grid(256 / QTILE, n);                 // (4, 2048)
    attn_kernel<<<grid, 256, SMEM_BYTES>>>(Q, K, V, L, W, O);
}

// round 6
// speedup vs baseline: 4.4720x; 4.4720x over previous
#include <cuda_runtime.h>
#include <cuda_bf16.h>
#include <cstdint>

// DotProductAttention, GB300 build path = generic sm_103 PTX -> use mma.sync (HMMA), not tcgen05.
// FlashAttention-style: 1 CTA/batch, 8 warps x 32 q-rows, kv chunks of 64, online softmax.
// bf16 3-split (hi*hi + hi*lo + lo*hi) for both S=QK^T and O=PV; fp32 accumulate.
// inputs: [0] Q f32 (2048,256,64) [1] K f32 [2] V f32 [3] valid_lens i32 (2048)
//         [4] window_mask f32 (64,256,256);  output f32 (2048,256,64)

namespace {

constexpr int SMEM_BYTES = 6 * 32768;   // QH QL KH KL VH VL, each 256x64 bf16 (128B rows)

#define SW(o) ((o) ^ ((((uint32_t)(o)) >> 3) & 0x70u))

__device__ __forceinline__ uint32_t smem_u32(const void* p) {
    uint32_t a;
    asm("{ .reg .u64 t; cvta.to.shared.u64 t, %1; cvt.u32.u64 %0, t; }" : "=r"(a) : "l"(p));
    return a;
}
__device__ __forceinline__ void ldsm4(uint32_t r[4], uint32_t a) {
    asm volatile("ldmatrix.sync.aligned.m8n8.x4.shared.b16 {%0,%1,%2,%3}, [%4];"
                 : "=r"(r[0]), "=r"(r[1]), "=r"(r[2]), "=r"(r[3]) : "r"(a));
}
__device__ __forceinline__ void ldsm4t(uint32_t r[4], uint32_t a) {
    asm volatile("ldmatrix.sync.aligned.m8n8.x4.trans.shared.b16 {%0,%1,%2,%3}, [%4];"
                 : "=r"(r[0]), "=r"(r[1]), "=r"(r[2]), "=r"(r[3]) : "r"(a));
}
__device__ __forceinline__ void mmabf(float c[4], const uint32_t a[4], uint32_t b0, uint32_t b1) {
    asm volatile("mma.sync.aligned.m16n8k16.row.col.f32.bf16.bf16.f32 "
                 "{%0,%1,%2,%3}, {%4,%5,%6,%7}, {%8,%9}, {%0,%1,%2,%3};"
                 : "+f"(c[0]), "+f"(c[1]), "+f"(c[2]), "+f"(c[3])
                 : "r"(a[0]), "r"(a[1]), "r"(a[2]), "r"(a[3]), "r"(b0), "r"(b1));
}
__device__ __forceinline__ void split2(float a, float b, uint32_t& hi, uint32_t& lo) {
    __nv_bfloat16 ha = __float2bfloat16_rn(a), hb = __float2bfloat16_rn(b);
    float la = a - __bfloat162float(ha);
    float lb = b - __bfloat162float(hb);
    hi = (uint32_t)__bfloat16_as_ushort(ha) | ((uint32_t)__bfloat16_as_ushort(hb) << 16);
    lo = (uint32_t)__bfloat16_as_ushort(__float2bfloat16_rn(la)) |
         ((uint32_t)__bfloat16_as_ushort(__float2bfloat16_rn(lb)) << 16);
}

__global__ __launch_bounds__(256, 1)
void attn_mma(const float* __restrict__ Qg, const float* __restrict__ Kg,
              const float* __restrict__ Vg, const int*   __restrict__ Lg,
              const float* __restrict__ Wg, float* __restrict__ Og)
{
    extern __shared__ char smem[];
    char* sQHp = smem;             char* sQLp = smem + 32768;
    char* sKHp = smem + 65536;     char* sKLp = smem + 98304;
    char* sVHp = smem + 131072;    char* sVLp = smem + 163840;

    const int tid = threadIdx.x, wid = tid >> 5, lane = tid & 31;
    const int b   = blockIdx.x;
    const int w   = (b >> 3) & 63;
    const int len = Lg[b];
    const int q0w = wid * 32;
    const int rg  = lane >> 2, cp = lane & 3;

    // ---------- preprocess: fp32 -> bf16 hi/lo into SW128 smem ----------
    {
        const float4* Q4 = (const float4*)(Qg + (size_t)b * 16384);
        const float4* K4 = (const float4*)(Kg + (size_t)b * 16384);
        const float4* V4 = (const float4*)(Vg + (size_t)b * 16384);
        #pragma unroll
        for (int it = 0; it < 16; ++it) {
            int idx = tid + it * 256;
            int r = idx >> 4, c4 = idx & 15;
            uint32_t off = SW((uint32_t)(r * 128 + c4 * 8));
            uint32_t h0, l0, h1, l1;
            float4 q = Q4[idx];
            split2(q.x, q.y, h0, l0); split2(q.z, q.w, h1, l1);
            *(uint2*)(sQHp + off) = make_uint2(h0, h1);
            *(uint2*)(sQLp + off) = make_uint2(l0, l1);
            float4 k = K4[idx];
            split2(k.x, k.y, h0, l0); split2(k.z, k.w, h1, l1);
            *(uint2*)(sKHp + off) = make_uint2(h0, h1);
            *(uint2*)(sKLp + off) = make_uint2(l0, l1);
            float4 v = V4[idx];
            split2(v.x, v.y, h0, l0); split2(v.z, v.w, h1, l1);
            *(uint2*)(sVHp + off) = make_uint2(h0, h1);
            *(uint2*)(sVLp + off) = make_uint2(l0, l1);
        }
    }
    __syncthreads();

    const uint32_t sQH = smem_u32(sQHp), sQL = smem_u32(sQLp);
    const uint32_t sKH = smem_u32(sKHp), sKL = smem_u32(sKLp);
    const uint32_t sVH = smem_u32(sVHp), sVL = smem_u32(sVLp);

    // per-lane ldmatrix address components (pre-swizzle byte offsets)
    const uint32_t qrowb = (uint32_t)((q0w + (lane & 15)) * 128 + ((lane >> 4) & 1) * 16);
    const uint32_t krowb = (uint32_t)((((lane & 7) + ((lane >> 4) & 1) * 8)) * 128 + ((lane >> 3) & 1) * 16);
    const uint32_t vrowb = (uint32_t)((((lane & 7) + ((lane >> 3) & 1) * 8)) * 128 + ((lane >> 4) & 1) * 16);

    float oa[2][8][4];
    #pragma unroll
    for (int mt = 0; mt < 2; ++mt)
        #pragma unroll
        for (int dt = 0; dt < 8; ++dt)
            #pragma unroll
            for (int i = 0; i < 4; ++i) oa[mt][dt][i] = 0.0f;

    float mrow[2][2] = {{-1e30f, -1e30f}, {-1e30f, -1e30f}};
    float lrow[2][2] = {{0.0f, 0.0f}, {0.0f, 0.0f}};

    #pragma unroll 1
    for (int c = 0; c < 4; ++c) {
        const int kvb = c * 64;

        // ---------- S = Q K^T (32x64 per warp), bf16 3-split ----------
        float sa[2][8][4];
        #pragma unroll
        for (int mt = 0; mt < 2; ++mt)
            #pragma unroll
            for (int nt = 0; nt < 8; ++nt)
                #pragma unroll
                for (int i = 0; i < 4; ++i) sa[mt][nt][i] = 0.0f;

        #pragma unroll
        for (int ks = 0; ks < 4; ++ks) {
            uint32_t aH[2][4], aL[2][4], bb[4][4];
            #pragma unroll
            for (int mt = 0; mt < 2; ++mt) {
                uint32_t off = SW(qrowb + (uint32_t)(mt * 2048 + ks * 32));
                ldsm4(aH[mt], sQH + off);
                ldsm4(aL[mt], sQL + off);
            }
            #pragma unroll
            for (int np = 0; np < 4; ++np) {
                uint32_t off = SW(krowb + (uint32_t)((kvb + np * 16) * 128 + ks * 32));
                ldsm4(bb[np], sKH + off);
            }
            #pragma unroll
            for (int np = 0; np < 4; ++np)
                #pragma unroll
                for (int mt = 0; mt < 2; ++mt) {
                    mmabf(sa[mt][2 * np],     aH[mt], bb[np][0], bb[np][1]);
                    mmabf(sa[mt][2 * np + 1], aH[mt], bb[np][2], bb[np][3]);
                    mmabf(sa[mt][2 * np],     aL[mt], bb[np][0], bb[np][1]);
                    mmabf(sa[mt][2 * np + 1], aL[mt], bb[np][2], bb[np][3]);
                }
            #pragma unroll
            for (int np = 0; np < 4; ++np) {
                uint32_t off = SW(krowb + (uint32_t)((kvb + np * 16) * 128 + ks * 32));
                ldsm4(bb[np], sKL + off);
            }
            #pragma unroll
            for (int np = 0; np < 4; ++np)
                #pragma unroll
                for (int mt = 0; mt < 2; ++mt) {
                    mmabf(sa[mt][2 * np],     aH[mt], bb[np][0], bb[np][1]);
                    mmabf(sa[mt][2 * np + 1], aH[mt], bb[np][2], bb[np][3]);
                }
        }

        // ---------- scale + window mask + valid mask + chunk max ----------
        float mc[2][2] = {{-1e30f, -1e30f}, {-1e30f, -1e30f}};
        const float* Wb = Wg + (size_t)(w * 256) * 256;
        #pragma unroll
        for (int mt = 0; mt < 2; ++mt) {
            const int r0 = q0w + mt * 16 + rg;
            #pragma unroll
            for (int nt = 0; nt < 8; ++nt) {
                const int col = kvb + nt * 8 + cp * 2;
                float2 w0 = *(const float2*)(Wb + (size_t)r0 * 256 + col);
                float2 w1 = *(const float2*)(Wb + (size_t)(r0 + 8) * 256 + col);
                float x0 = fmaf(sa[mt][nt][0], 0.125f, w0.x);
                float x1 = fmaf(sa[mt][nt][1], 0.125f, w0.y);
                float x2 = fmaf(sa[mt][nt][2], 0.125f, w1.x);
                float x3 = fmaf(sa[mt][nt][3], 0.125f, w1.y);
                if (col >= len)     { x0 = -1.0e6f; x2 = -1.0e6f; }
                if (col + 1 >= len) { x1 = -1.0e6f; x3 = -1.0e6f; }
                sa[mt][nt][0] = x0; sa[mt][nt][1] = x1;
                sa[mt][nt][2] = x2; sa[mt][nt][3] = x3;
                mc[mt][0] = fmaxf(mc[mt][0], fmaxf(x0, x1));
                mc[mt][1] = fmaxf(mc[mt][1], fmaxf(x2, x3));
            }
        }

        // ---------- online softmax update ----------
        float scl[2][2];
        #pragma unroll
        for (int mt = 0; mt < 2; ++mt)
            #pragma unroll
            for (int h = 0; h < 2; ++h) {
                float m = mc[mt][h];
                m = fmaxf(m, __shfl_xor_sync(0xffffffffu, m, 1));
                m = fmaxf(m, __shfl_xor_sync(0xffffffffu, m, 2));
                float mn = fmaxf(mrow[mt][h], m);
                scl[mt][h] = __expf(mrow[mt][h] - mn);   // 0 on first chunk (mrow = -1e30)
                mrow[mt][h] = mn;
            }

        float lc[2][2] = {{0.0f, 0.0f}, {0.0f, 0.0f}};
        #pragma unroll
        for (int mt = 0; mt < 2; ++mt)
            #pragma unroll
            for (int nt = 0; nt < 8; ++nt) {
                float p0 = __expf(sa[mt][nt][0] - mrow[mt][0]);
                float p1 = __expf(sa[mt][nt][1] - mrow[mt][0]);
                float p2 = __expf(sa[mt][nt][2] - mrow[mt][1]);
                float p3 = __expf(sa[mt][nt][3] - mrow[mt][1]);
                sa[mt][nt][0] = p0; sa[mt][nt][1] = p1;
                sa[mt][nt][2] = p2; sa[mt][nt][3] = p3;
                lc[mt][0] += p0 + p1;
                lc[mt][1] += p2 + p3;
            }
        #pragma unroll
        for (int mt = 0; mt < 2; ++mt)
            #pragma unroll
            for (int h = 0; h < 2; ++h) {
                float l = lc[mt][h];
                l += __shfl_xor_sync(0xffffffffu, l, 1);
                l += __shfl_xor_sync(0xffffffffu, l, 2);
                lrow[mt][h] = lrow[mt][h] * scl[mt][h] + l;
            }
        #pragma unroll
        for (int mt = 0; mt < 2; ++mt)
            #pragma unroll
            for (int dt = 0; dt < 8; ++dt) {
                oa[mt][dt][0] *= scl[mt][0];
                oa[mt][dt][1] *= scl[mt][0];
                oa[mt][dt][2] *= scl[mt][1];
                oa[mt][dt][3] *= scl[mt][1];
            }

        // ---------- O += P V (P from S accs, no smem roundtrip), 3-split ----------
        #pragma unroll
        for (int kk = 0; kk < 4; ++kk) {
            uint32_t paH[2][4], paL[2][4];
            #pragma unroll
            for (int mt = 0; mt < 2; ++mt)
                #pragma unroll
                for (int j = 0; j < 2; ++j) {
                    const float* p = sa[mt][2 * kk + j];
                    __nv_bfloat16 h0 = __float2bfloat16_rn(p[0]);
                    __nv_bfloat16 h1 = __float2bfloat16_rn(p[1]);
                    __nv_bfloat16 h2 = __float2bfloat16_rn(p[2]);
                    __nv_bfloat16 h3 = __float2bfloat16_rn(p[3]);
                    paH[mt][2 * j]     = (uint32_t)__bfloat16_as_ushort(h0) | ((uint32_t)__bfloat16_as_ushort(h1) << 16);
                    paH[mt][2 * j + 1] = (uint32_t)__bfloat16_as_ushort(h2) | ((uint32_t)__bfloat16_as_ushort(h3) << 16);
                    __nv_bfloat16 g0 = __float2bfloat16_rn(p[0] - __bfloat162float(h0));
                    __nv_bfloat16 g1 = __float2bfloat16_rn(p[1] - __bfloat162float(h1));
                    __nv_bfloat16 g2 = __float2bfloat16_rn(p[2] - __bfloat162float(h2));
                    __nv_bfloat16 g3 = __float2bfloat16_rn(p[3] - __bfloat162float(h3));
                    paL[mt][2 * j]     = (uint32_t)__bfloat16_as_ushort(g0) | ((uint32_t)__bfloat16_as_ushort(g1) << 16);
                    paL[mt][2 * j + 1] = (uint32_t)__bfloat16_as_ushort(g2) | ((uint32_t)__bfloat16_as_ushort(g3) << 16);
                }
            uint32_t bb[4][4];
            #pragma unroll
            for (int dp = 0; dp < 4; ++dp) {
                uint32_t off = SW(vrowb + (uint32_t)((kvb + kk * 16) * 128 + dp * 32));
                ldsm4t(bb[dp], sVH + off);
            }
            #pragma unroll
            for (int dp = 0; dp < 4; ++dp)
                #pragma unroll
                for (int mt = 0; mt < 2; ++mt) {
                    mmabf(oa[mt][2 * dp],     paH[mt], bb[dp][0], bb[dp][1]);
                    mmabf(oa[mt][2 * dp + 1], paH[mt], bb[dp][2], bb[dp][3]);
                    mmabf(oa[mt][2 * dp],     paL[mt], bb[dp][0], bb[dp][1]);
                    mmabf(oa[mt][2 * dp + 1], paL[mt], bb[dp][2], bb[dp][3]);
                }
            #pragma unroll
            for (int dp = 0; dp < 4; ++dp) {
                uint32_t off = SW(vrowb + (uint32_t)((kvb + kk * 16) * 128 + dp * 32));
                ldsm4t(bb[dp], sVL + off);
            }
            #pragma unroll
            for (int dp = 0; dp < 4; ++dp)
                #pragma unroll
                for (int mt = 0; mt < 2; ++mt) {
                    mmabf(oa[mt][2 * dp],     paH[mt], bb[dp][0], bb[dp][1]);
                    mmabf(oa[mt][2 * dp + 1], paH[mt], bb[dp][2], bb[dp][3]);
                }
        }
    }

    // ---------- finalize: O /= l, store fp32 ----------
    float corr[2][2];
    #pragma unroll
    for (int mt = 0; mt < 2; ++mt)
        #pragma unroll
        for (int h = 0; h < 2; ++h) corr[mt][h] = 1.0f / lrow[mt][h];

    float* Ob = Og + (size_t)b * 16384;
    #pragma unroll
    for (int mt = 0; mt < 2; ++mt) {
        const int r0 = q0w + mt * 16 + rg;
        #pragma unroll
        for (int dt = 0; dt < 8; ++dt) {
            const int colo = dt * 8 + cp * 2;
            *(float2*)(Ob + (size_t)r0 * 64 + colo) =
                make_float2(oa[mt][dt][0] * corr[mt][0], oa[mt][dt][1] * corr[mt][0]);
            *(float2*)(Ob + (size_t)(r0 + 8) * 64 + colo) =
                make_float2(oa[mt][dt][2] * corr[mt][1], oa[mt][dt][3] * corr[mt][1]);
        }
    }
}

} // namespace

extern "C" void kernel_launch(void* const* d_in, const int* in_sizes, int n_in,
                              void* d_out, int out_size)
{
    const float* Q = (const float*)d_in[0];
    const float* K = (const float*)d_in[1];
    const float* V = (const float*)d_in[2];
    const int*   L = (const int*)  d_in[3];
    const float* W = (const float*)d_in[4];
    float*       O = (float*)d_out;

    const int n = in_sizes[0] / (256 * 64);   // 2048 batches

    cudaFuncSetAttribute(attn_mma, cudaFuncAttributeMaxDynamicSharedMemorySize, SMEM_BYTES);
    attn_mma<<<n, 256, SMEM_BYTES>>>(Q, K, V, L, W, O);
}

// round 7
// speedup vs baseline: 4.9084x; 1.0976x over previous
#include <cuda_runtime.h>
#include <cuda_bf16.h>
#include <cstdint>

// DotProductAttention, sm_103 generic PTX path -> mma.sync (HMMA) FlashAttention.
// R7: 512 threads/CTA (16 warps, 4/SMSP) x 16 q-rows/warp, 1 batch/CTA.
// bf16 3-split (HH+HL+LH) for S=QK^T and O=PV; fp32 accumulate; online softmax in log2 domain.
// inputs: [0] Q f32 (2048,256,64) [1] K f32 [2] V f32 [3] valid_lens i32 (2048)
//         [4] window_mask f32 (64,256,256);  output f32 (2048,256,64)

namespace {

constexpr int SMEM_BYTES = 6 * 32768;   // QH QL KH KL VH VL, each 256x64 bf16 (128B rows)
constexpr float LOG2E = 1.4426950408889634f;
constexpr float QSCL  = 0.125f * LOG2E;   // folded into Q at preprocess
constexpr float NEG_BIG = -1442695.04f;   // -1e6 * log2e (masked-score in log2 domain)

#define SW(o) ((o) ^ ((((uint32_t)(o)) >> 3) & 0x70u))

__device__ __forceinline__ uint32_t smem_u32(const void* p) {
    uint32_t a;
    asm("{ .reg .u64 t; cvta.to.shared.u64 t, %1; cvt.u32.u64 %0, t; }" : "=r"(a) : "l"(p));
    return a;
}
__device__ __forceinline__ void ldsm4(uint32_t r[4], uint32_t a) {
    asm volatile("ldmatrix.sync.aligned.m8n8.x4.shared.b16 {%0,%1,%2,%3}, [%4];"
                 : "=r"(r[0]), "=r"(r[1]), "=r"(r[2]), "=r"(r[3]) : "r"(a));
}
__device__ __forceinline__ void ldsm4t(uint32_t r[4], uint32_t a) {
    asm volatile("ldmatrix.sync.aligned.m8n8.x4.trans.shared.b16 {%0,%1,%2,%3}, [%4];"
                 : "=r"(r[0]), "=r"(r[1]), "=r"(r[2]), "=r"(r[3]) : "r"(a));
}
__device__ __forceinline__ void mmabf(float c[4], const uint32_t a[4], uint32_t b0, uint32_t b1) {
    asm volatile("mma.sync.aligned.m16n8k16.row.col.f32.bf16.bf16.f32 "
                 "{%0,%1,%2,%3}, {%4,%5,%6,%7}, {%8,%9}, {%0,%1,%2,%3};"
                 : "+f"(c[0]), "+f"(c[1]), "+f"(c[2]), "+f"(c[3])
                 : "r"(a[0]), "r"(a[1]), "r"(a[2]), "r"(a[3]), "r"(b0), "r"(b1));
}
__device__ __forceinline__ void split2(float a, float b, uint32_t& hi, uint32_t& lo) {
    __nv_bfloat16 ha = __float2bfloat16_rn(a), hb = __float2bfloat16_rn(b);
    float la = a - __bfloat162float(ha);
    float lb = b - __bfloat162float(hb);
    hi = (uint32_t)__bfloat16_as_ushort(ha) | ((uint32_t)__bfloat16_as_ushort(hb) << 16);
    lo = (uint32_t)__bfloat16_as_ushort(__float2bfloat16_rn(la)) |
         ((uint32_t)__bfloat16_as_ushort(__float2bfloat16_rn(lb)) << 16);
}

__global__ __launch_bounds__(512, 1)
void attn_mma(const float* __restrict__ Qg, const float* __restrict__ Kg,
              const float* __restrict__ Vg, const int*   __restrict__ Lg,
              const float* __restrict__ Wg, float* __restrict__ Og)
{
    extern __shared__ char smem[];
    char* sQHp = smem;             char* sQLp = smem + 32768;
    char* sKHp = smem + 65536;     char* sKLp = smem + 98304;
    char* sVHp = smem + 131072;    char* sVLp = smem + 163840;

    const int tid = threadIdx.x, wid = tid >> 5, lane = tid & 31;
    const int b   = blockIdx.x;
    const int w   = (b >> 3) & 63;
    const int len = Lg[b];
    const int q0w = wid * 16;            // 16 q-rows per warp
    const int rg  = lane >> 2, cp = lane & 3;

    // ---------- preprocess: fp32 -> bf16 hi/lo into SW128 smem (Q pre-scaled) ----------
    {
        const float4* Q4 = (const float4*)(Qg + (size_t)b * 16384);
        const float4* K4 = (const float4*)(Kg + (size_t)b * 16384);
        const float4* V4 = (const float4*)(Vg + (size_t)b * 16384);
        #pragma unroll
        for (int it = 0; it < 8; ++it) {
            int idx = tid + it * 512;
            int r = idx >> 4, c4 = idx & 15;
            uint32_t off = SW((uint32_t)(r * 128 + c4 * 8));
            uint32_t h0, l0, h1, l1;
            float4 q = Q4[idx];
            split2(q.x * QSCL, q.y * QSCL, h0, l0);
            split2(q.z * QSCL, q.w * QSCL, h1, l1);
            *(uint2*)(sQHp + off) = make_uint2(h0, h1);
            *(uint2*)(sQLp + off) = make_uint2(l0, l1);
            float4 k = K4[idx];
            split2(k.x, k.y, h0, l0); split2(k.z, k.w, h1, l1);
            *(uint2*)(sKHp + off) = make_uint2(h0, h1);
            *(uint2*)(sKLp + off) = make_uint2(l0, l1);
            float4 v = V4[idx];
            split2(v.x, v.y, h0, l0); split2(v.z, v.w, h1, l1);
            *(uint2*)(sVHp + off) = make_uint2(h0, h1);
            *(uint2*)(sVLp + off) = make_uint2(l0, l1);
        }
    }
    __syncthreads();

    const uint32_t sQH = smem_u32(sQHp), sQL = smem_u32(sQLp);
    const uint32_t sKH = smem_u32(sKHp), sKL = smem_u32(sKLp);
    const uint32_t sVH = smem_u32(sVHp), sVL = smem_u32(sVLp);

    // per-lane ldmatrix base byte offsets (pre-swizzle)
    const uint32_t qrowb = (uint32_t)((q0w + (lane & 15)) * 128 + ((lane >> 4) & 1) * 16);
    const uint32_t krowb = (uint32_t)((((lane & 7) + ((lane >> 4) & 1) * 8)) * 128 + ((lane >> 3) & 1) * 16);
    const uint32_t vrowb = (uint32_t)((((lane & 7) + ((lane >> 3) & 1) * 8)) * 128 + ((lane >> 4) & 1) * 16);

    float oa[8][4];
    #pragma unroll
    for (int dt = 0; dt < 8; ++dt)
        #pragma unroll
        for (int i = 0; i < 4; ++i) oa[dt][i] = 0.0f;

    float mrow[2] = {-1e30f, -1e30f};
    float lrow[2] = {0.0f, 0.0f};

    #pragma unroll 1
    for (int c = 0; c < 4; ++c) {
        const int kvb = c * 64;

        // ---------- S = Q K^T (16x64 per warp, already x log2e/8), bf16 3-split ----------
        float sa[8][4];
        #pragma unroll
        for (int nt = 0; nt < 8; ++nt)
            #pragma unroll
            for (int i = 0; i < 4; ++i) sa[nt][i] = 0.0f;

        #pragma unroll
        for (int ks = 0; ks < 4; ++ks) {
            uint32_t aH[4], aL[4], bb[4][4];
            {
                uint32_t off = SW(qrowb + (uint32_t)(ks * 32));
                ldsm4(aH, sQH + off);
                ldsm4(aL, sQL + off);
            }
            #pragma unroll
            for (int np = 0; np < 4; ++np) {
                uint32_t off = SW(krowb + (uint32_t)((kvb + np * 16) * 128 + ks * 32));
                ldsm4(bb[np], sKH + off);
            }
            #pragma unroll
            for (int np = 0; np < 4; ++np) {
                mmabf(sa[2 * np],     aH, bb[np][0], bb[np][1]);
                mmabf(sa[2 * np + 1], aH, bb[np][2], bb[np][3]);
                mmabf(sa[2 * np],     aL, bb[np][0], bb[np][1]);
                mmabf(sa[2 * np + 1], aL, bb[np][2], bb[np][3]);
            }
            #pragma unroll
            for (int np = 0; np < 4; ++np) {
                uint32_t off = SW(krowb + (uint32_t)((kvb + np * 16) * 128 + ks * 32));
                ldsm4(bb[np], sKL + off);
            }
            #pragma unroll
            for (int np = 0; np < 4; ++np) {
                mmabf(sa[2 * np],     aH, bb[np][0], bb[np][1]);
                mmabf(sa[2 * np + 1], aH, bb[np][2], bb[np][3]);
            }
        }

        // ---------- + window_mask*log2e + valid mask + chunk max (log2 domain) ----------
        float mc[2] = {-1e30f, -1e30f};
        const float* Wb = Wg + (size_t)(w * 256) * 256;
        {
            const int r0 = q0w + rg;
            #pragma unroll
            for (int nt = 0; nt < 8; ++nt) {
                const int col = kvb + nt * 8 + cp * 2;
                float2 w0 = *(const float2*)(Wb + (size_t)r0 * 256 + col);
                float2 w1 = *(const float2*)(Wb + (size_t)(r0 + 8) * 256 + col);
                float x0 = fmaf(w0.x, LOG2E, sa[nt][0]);
                float x1 = fmaf(w0.y, LOG2E, sa[nt][1]);
                float x2 = fmaf(w1.x, LOG2E, sa[nt][2]);
                float x3 = fmaf(w1.y, LOG2E, sa[nt][3]);
                if (col >= len)     { x0 = NEG_BIG; x2 = NEG_BIG; }
                if (col + 1 >= len) { x1 = NEG_BIG; x3 = NEG_BIG; }
                sa[nt][0] = x0; sa[nt][1] = x1;
                sa[nt][2] = x2; sa[nt][3] = x3;
                mc[0] = fmaxf(mc[0], fmaxf(x0, x1));
                mc[1] = fmaxf(mc[1], fmaxf(x2, x3));
            }
        }

        // ---------- online softmax update ----------
        float scl[2];
        #pragma unroll
        for (int h = 0; h < 2; ++h) {
            float m = mc[h];
            m = fmaxf(m, __shfl_xor_sync(0xffffffffu, m, 1));
            m = fmaxf(m, __shfl_xor_sync(0xffffffffu, m, 2));
            float mn = fmaxf(mrow[h], m);
            scl[h] = exp2f(mrow[h] - mn);   // 0 on first chunk
            mrow[h] = mn;
        }

        float lc[2] = {0.0f, 0.0f};
        #pragma unroll
        for (int nt = 0; nt < 8; ++nt) {
            float p0 = exp2f(sa[nt][0] - mrow[0]);
            float p1 = exp2f(sa[nt][1] - mrow[0]);
            float p2 = exp2f(sa[nt][2] - mrow[1]);
            float p3 = exp2f(sa[nt][3] - mrow[1]);
            sa[nt][0] = p0; sa[nt][1] = p1;
            sa[nt][2] = p2; sa[nt][3] = p3;
            lc[0] += p0 + p1;
            lc[1] += p2 + p3;
        }
        #pragma unroll
        for (int h = 0; h < 2; ++h) {
            float l = lc[h];
            l += __shfl_xor_sync(0xffffffffu, l, 1);
            l += __shfl_xor_sync(0xffffffffu, l, 2);
            lrow[h] = lrow[h] * scl[h] + l;
        }
        #pragma unroll
        for (int dt = 0; dt < 8; ++dt) {
            oa[dt][0] *= scl[0];
            oa[dt][1] *= scl[0];
            oa[dt][2] *= scl[1];
            oa[dt][3] *= scl[1];
        }

        // ---------- O += P V (P straight from S accumulators), bf16 3-split ----------
        #pragma unroll
        for (int kk = 0; kk < 4; ++kk) {
            uint32_t paH[4], paL[4];
            #pragma unroll
            for (int j = 0; j < 2; ++j) {
                const float* p = sa[2 * kk + j];
                __nv_bfloat16 h0 = __float2bfloat16_rn(p[0]);
                __nv_bfloat16 h1 = __float2bfloat16_rn(p[1]);
                __nv_bfloat16 h2 = __float2bfloat16_rn(p[2]);
                __nv_bfloat16 h3 = __float2bfloat16_rn(p[3]);
                paH[2 * j]     = (uint32_t)__bfloat16_as_ushort(h0) | ((uint32_t)__bfloat16_as_ushort(h1) << 16);
                paH[2 * j + 1] = (uint32_t)__bfloat16_as_ushort(h2) | ((uint32_t)__bfloat16_as_ushort(h3) << 16);
                __nv_bfloat16 g0 = __float2bfloat16_rn(p[0] - __bfloat162float(h0));
                __nv_bfloat16 g1 = __float2bfloat16_rn(p[1] - __bfloat162float(h1));
                __nv_bfloat16 g2 = __float2bfloat16_rn(p[2] - __bfloat162float(h2));
                __nv_bfloat16 g3 = __float2bfloat16_rn(p[3] - __bfloat162float(h3));
                paL[2 * j]     = (uint32_t)__bfloat16_as_ushort(g0) | ((uint32_t)__bfloat16_as_ushort(g1) << 16);
                paL[2 * j + 1] = (uint32_t)__bfloat16_as_ushort(g2) | ((uint32_t)__bfloat16_as_ushort(g3) << 16);
            }
            uint32_t bb[4][4];
            #pragma unroll
            for (int dp = 0; dp < 4; ++dp) {
                uint32_t off = SW(vrowb + (uint32_t)((kvb + kk * 16) * 128 + dp * 32));
                ldsm4t(bb[dp], sVH + off);
            }
            #pragma unroll
            for (int dp = 0; dp < 4; ++dp) {
                mmabf(oa[2 * dp],     paH, bb[dp][0], bb[dp][1]);
                mmabf(oa[2 * dp + 1], paH, bb[dp][2], bb[dp][3]);
                mmabf(oa[2 * dp],     paL, bb[dp][0], bb[dp][1]);
                mmabf(oa[2 * dp + 1], paL, bb[dp][2], bb[dp][3]);
            }
            #pragma unroll
            for (int dp = 0; dp < 4; ++dp) {
                uint32_t off = SW(vrowb + (uint32_t)((kvb + kk * 16) * 128 + dp * 32));
                ldsm4t(bb[dp], sVL + off);
            }
            #pragma unroll
            for (int dp = 0; dp < 4; ++dp) {
                mmabf(oa[2 * dp],     paH, bb[dp][0], bb[dp][1]);
                mmabf(oa[2 * dp + 1], paH, bb[dp][2], bb[dp][3]);
            }
        }
    }

    // ---------- finalize: O /= l, store fp32 ----------
    float corr[2] = {1.0f / lrow[0], 1.0f / lrow[1]};

    float* Ob = Og + (size_t)b * 16384;
    {
        const int r0 = q0w + rg;
        #pragma unroll
        for (int dt = 0; dt < 8; ++dt) {
            const int colo = dt * 8 + cp * 2;
            *(float2*)(Ob + (size_t)r0 * 64 + colo) =
                make_float2(oa[dt][0] * corr[0], oa[dt][1] * corr[0]);
            *(float2*)(Ob + (size_t)(r0 + 8) * 64 + colo) =
                make_float2(oa[dt][2] * corr[1], oa[dt][3] * corr[1]);
        }
    }
}

} // namespace

extern "C" void kernel_launch(void* const* d_in, const int* in_sizes, int n_in,
                              void* d_out, int out_size)
{
    const float* Q = (const float*)d_in[0];
    const float* K = (const float*)d_in[1];
    const float* V = (const float*)d_in[2];
    const int*   L = (const int*)  d_in[3];
    const float* W = (const float*)d_in[4];
    float*       O = (float*)d_out;

    const int n = in_sizes[0] / (256 * 64);   // 2048 batches

    cudaFuncSetAttribute(attn_mma, cudaFuncAttributeMaxDynamicSharedMemorySize, SMEM_BYTES);
    attn_mma<<<n, 512, SMEM_BYTES>>>(Q, K, V, L, W, O);
}

// round 8
// speedup vs baseline: 4.9407x; 1.0066x over previous
#include <cuda_runtime.h>
#include <cuda_bf16.h>
#include <cstdint>

// DotProductAttention, sm_103 generic PTX path -> mma.sync (HMMA) FlashAttention.
// R8: mask preloaded as S-accumulator init; ex2.approx; batched ldsm; bf16x2 cvt.
// 512 threads/CTA (16 warps) x 16 q-rows/warp, 1 batch/CTA, kv chunks of 64.
// bf16 3-split (HH+HL+LH) for S=QK^T and O=PV; fp32 accumulate; log2-domain softmax.

namespace {

constexpr int SMEM_BYTES = 6 * 32768;   // QH QL KH KL VH VL, each 256x64 bf16 (128B rows)
constexpr float LOG2E   = 1.4426950408889634f;
constexpr float QSCL    = 0.125f * LOG2E;   // folded into Q at preprocess
constexpr float NEG_BIG = -1442695.04f;     // -1e6 * log2e

#define SW(o) ((o) ^ ((((uint32_t)(o)) >> 3) & 0x70u))

__device__ __forceinline__ uint32_t smem_u32(const void* p) {
    uint32_t a;
    asm("{ .reg .u64 t; cvta.to.shared.u64 t, %1; cvt.u32.u64 %0, t; }" : "=r"(a) : "l"(p));
    return a;
}
__device__ __forceinline__ void ldsm4(uint32_t r[4], uint32_t a) {
    asm volatile("ldmatrix.sync.aligned.m8n8.x4.shared.b16 {%0,%1,%2,%3}, [%4];"
                 : "=r"(r[0]), "=r"(r[1]), "=r"(r[2]), "=r"(r[3]) : "r"(a));
}
__device__ __forceinline__ void ldsm4t(uint32_t r[4], uint32_t a) {
    asm volatile("ldmatrix.sync.aligned.m8n8.x4.trans.shared.b16 {%0,%1,%2,%3}, [%4];"
                 : "=r"(r[0]), "=r"(r[1]), "=r"(r[2]), "=r"(r[3]) : "r"(a));
}
__device__ __forceinline__ void mmabf(float c[4], const uint32_t a[4], uint32_t b0, uint32_t b1) {
    asm volatile("mma.sync.aligned.m16n8k16.row.col.f32.bf16.bf16.f32 "
                 "{%0,%1,%2,%3}, {%4,%5,%6,%7}, {%8,%9}, {%0,%1,%2,%3};"
                 : "+f"(c[0]), "+f"(c[1]), "+f"(c[2]), "+f"(c[3])
                 : "r"(a[0]), "r"(a[1]), "r"(a[2]), "r"(a[3]), "r"(b0), "r"(b1));
}
// packed bf16x2: low half = bf16(lo), high half = bf16(hi)
__device__ __forceinline__ uint32_t cvt2(float lo, float hi) {
    uint32_t r;
    asm("cvt.rn.bf16x2.f32 %0, %1, %2;" : "=r"(r) : "f"(hi), "f"(lo));
    return r;
}
__device__ __forceinline__ float ex2(float x) {
    float y;
    asm("ex2.approx.f32 %0, %1;" : "=f"(y) : "f"(x));
    return y;
}
// split two floats into packed bf16 hi pair + residual lo pair
__device__ __forceinline__ void split2(float a, float b, uint32_t& hi, uint32_t& lo) {
    hi = cvt2(a, b);
    float ra = a - __uint_as_float(hi << 16);
    float rb = b - __uint_as_float(hi & 0xFFFF0000u);
    lo = cvt2(ra, rb);
}

__global__ __launch_bounds__(512, 1)
void attn_mma(const float* __restrict__ Qg, const float* __restrict__ Kg,
              const float* __restrict__ Vg, const int*   __restrict__ Lg,
              const float* __restrict__ Wg, float* __restrict__ Og)
{
    extern __shared__ char smem[];
    char* sQHp = smem;             char* sQLp = smem + 32768;
    char* sKHp = smem + 65536;     char* sKLp = smem + 98304;
    char* sVHp = smem + 131072;    char* sVLp = smem + 163840;

    const int tid = threadIdx.x, wid = tid >> 5, lane = tid & 31;
    const int b   = blockIdx.x;
    const int w   = (b >> 3) & 63;
    const int len = Lg[b];
    const int q0w = wid * 16;
    const int rg  = lane >> 2, cp = lane & 3;

    // ---------- preprocess: fp32 -> bf16 hi/lo into SW128 smem (Q pre-scaled) ----------
    {
        const float4* Q4 = (const float4*)(Qg + (size_t)b * 16384);
        const float4* K4 = (const float4*)(Kg + (size_t)b * 16384);
        const float4* V4 = (const float4*)(Vg + (size_t)b * 16384);
        #pragma unroll
        for (int it = 0; it < 8; ++it) {
            int idx = tid + it * 512;
            int r = idx >> 4, c4 = idx & 15;
            uint32_t off = SW((uint32_t)(r * 128 + c4 * 8));
            uint32_t h0, l0, h1, l1;
            float4 q = Q4[idx];
            split2(q.x * QSCL, q.y * QSCL, h0, l0);
            split2(q.z * QSCL, q.w * QSCL, h1, l1);
            *(uint2*)(sQHp + off) = make_uint2(h0, h1);
            *(uint2*)(sQLp + off) = make_uint2(l0, l1);
            float4 k = K4[idx];
            split2(k.x, k.y, h0, l0); split2(k.z, k.w, h1, l1);
            *(uint2*)(sKHp + off) = make_uint2(h0, h1);
            *(uint2*)(sKLp + off) = make_uint2(l0, l1);
            float4 v = V4[idx];
            split2(v.x, v.y, h0, l0); split2(v.z, v.w, h1, l1);
            *(uint2*)(sVHp + off) = make_uint2(h0, h1);
            *(uint2*)(sVLp + off) = make_uint2(l0, l1);
        }
    }
    __syncthreads();

    const uint32_t sQH = smem_u32(sQHp), sQL = smem_u32(sQLp);
    const uint32_t sKH = smem_u32(sKHp), sKL = smem_u32(sKLp);
    const uint32_t sVH = smem_u32(sVHp), sVL = smem_u32(sVLp);

    const uint32_t qrowb = (uint32_t)((q0w + (lane & 15)) * 128 + ((lane >> 4) & 1) * 16);
    const uint32_t krowb = (uint32_t)((((lane & 7) + ((lane >> 4) & 1) * 8)) * 128 + ((lane >> 3) & 1) * 16);
    const uint32_t vrowb = (uint32_t)((((lane & 7) + ((lane >> 3) & 1) * 8)) * 128 + ((lane >> 4) & 1) * 16);

    float oa[8][4];
    #pragma unroll
    for (int dt = 0; dt < 8; ++dt)
        #pragma unroll
        for (int i = 0; i < 4; ++i) oa[dt][i] = 0.0f;

    float mrow[2] = {-1e30f, -1e30f};
    float lrow[2] = {0.0f, 0.0f};

    const float* Wb = Wg + (size_t)(w * 256) * 256;
    const int r0 = q0w + rg;

    #pragma unroll 1
    for (int c = 0; c < 4; ++c) {
        const int kvb = c * 64;

        // ---------- init S accumulators with window_mask*log2e (LDGs issue early,
        //            96 HMMAs below cover the L2 latency) ----------
        float sa[8][4];
        #pragma unroll
        for (int nt = 0; nt < 8; ++nt) {
            const int col = kvb + nt * 8 + cp * 2;
            float2 w0 = *(const float2*)(Wb + (size_t)r0 * 256 + col);
            float2 w1 = *(const float2*)(Wb + (size_t)(r0 + 8) * 256 + col);
            sa[nt][0] = w0.x * LOG2E;
            sa[nt][1] = w0.y * LOG2E;
            sa[nt][2] = w1.x * LOG2E;
            sa[nt][3] = w1.y * LOG2E;
        }

        // ---------- S += Q K^T (16x64 per warp, log2 units), bf16 3-split ----------
        #pragma unroll
        for (int ks = 0; ks < 4; ++ks) {
            uint32_t aH[4], aL[4], bh[4][4], bl[4][4];
            {
                uint32_t off = SW(qrowb + (uint32_t)(ks * 32));
                ldsm4(aH, sQH + off);
                ldsm4(aL, sQL + off);
            }
            #pragma unroll
            for (int np = 0; np < 4; ++np) {
                uint32_t off = SW(krowb + (uint32_t)((kvb + np * 16) * 128 + ks * 32));
                ldsm4(bh[np], sKH + off);
                ldsm4(bl[np], sKL + off);
            }
            #pragma unroll
            for (int np = 0; np < 4; ++np) {
                mmabf(sa[2 * np],     aH, bh[np][0], bh[np][1]);
                mmabf(sa[2 * np + 1], aH, bh[np][2], bh[np][3]);
                mmabf(sa[2 * np],     aL, bh[np][0], bh[np][1]);
                mmabf(sa[2 * np + 1], aL, bh[np][2], bh[np][3]);
                mmabf(sa[2 * np],     aH, bl[np][0], bl[np][1]);
                mmabf(sa[2 * np + 1], aH, bl[np][2], bl[np][3]);
            }
        }

        // ---------- valid mask + chunk max ----------
        float mc[2] = {-1e30f, -1e30f};
        #pragma unroll
        for (int nt = 0; nt < 8; ++nt) {
            const int col = kvb + nt * 8 + cp * 2;
            if (col >= len)     { sa[nt][0] = NEG_BIG; sa[nt][2] = NEG_BIG; }
            if (col + 1 >= len) { sa[nt][1] = NEG_BIG; sa[nt][3] = NEG_BIG; }
            mc[0] = fmaxf(mc[0], fmaxf(sa[nt][0], sa[nt][1]));
            mc[1] = fmaxf(mc[1], fmaxf(sa[nt][2], sa[nt][3]));
        }

        // ---------- online softmax update ----------
        float scl[2];
        #pragma unroll
        for (int h = 0; h < 2; ++h) {
            float m = mc[h];
            m = fmaxf(m, __shfl_xor_sync(0xffffffffu, m, 1));
            m = fmaxf(m, __shfl_xor_sync(0xffffffffu, m, 2));
            float mn = fmaxf(mrow[h], m);
            scl[h] = ex2(mrow[h] - mn);   // 0 on first chunk
            mrow[h] = mn;
        }

        float lc[2] = {0.0f, 0.0f};
        #pragma unroll
        for (int nt = 0; nt < 8; ++nt) {
            float p0 = ex2(sa[nt][0] - mrow[0]);
            float p1 = ex2(sa[nt][1] - mrow[0]);
            float p2 = ex2(sa[nt][2] - mrow[1]);
            float p3 = ex2(sa[nt][3] - mrow[1]);
            sa[nt][0] = p0; sa[nt][1] = p1;
            sa[nt][2] = p2; sa[nt][3] = p3;
            lc[0] += p0 + p1;
            lc[1] += p2 + p3;
        }
        #pragma unroll
        for (int h = 0; h < 2; ++h) {
            float l = lc[h];
            l += __shfl_xor_sync(0xffffffffu, l, 1);
            l += __shfl_xor_sync(0xffffffffu, l, 2);
            lrow[h] = lrow[h] * scl[h] + l;
        }
        #pragma unroll
        for (int dt = 0; dt < 8; ++dt) {
            oa[dt][0] *= scl[0];
            oa[dt][1] *= scl[0];
            oa[dt][2] *= scl[1];
            oa[dt][3] *= scl[1];
        }

        // ---------- O += P V (P straight from S accumulators), bf16 3-split ----------
        #pragma unroll
        for (int kk = 0; kk < 4; ++kk) {
            uint32_t vh[4][4], vl[4][4];
            #pragma unroll
            for (int dp = 0; dp < 4; ++dp) {
                uint32_t off = SW(vrowb + (uint32_t)((kvb + kk * 16) * 128 + dp * 32));
                ldsm4t(vh[dp], sVH + off);
                ldsm4t(vl[dp], sVL + off);
            }
            uint32_t paH[4], paL[4];
            #pragma unroll
            for (int j = 0; j < 2; ++j) {
                const float* p = sa[2 * kk + j];
                split2(p[0], p[1], paH[2 * j],     paL[2 * j]);
                split2(p[2], p[3], paH[2 * j + 1], paL[2 * j + 1]);
            }
            #pragma unroll
            for (int dp = 0; dp < 4; ++dp) {
                mmabf(oa[2 * dp],     paH, vh[dp][0], vh[dp][1]);
                mmabf(oa[2 * dp + 1], paH, vh[dp][2], vh[dp][3]);
                mmabf(oa[2 * dp],     paL, vh[dp][0], vh[dp][1]);
                mmabf(oa[2 * dp + 1], paL, vh[dp][2], vh[dp][3]);
                mmabf(oa[2 * dp],     paH, vl[dp][0], vl[dp][1]);
                mmabf(oa[2 * dp + 1], paH, vl[dp][2], vl[dp][3]);
            }
        }
    }

    // ---------- finalize: O /= l, store fp32 ----------
    float corr[2] = {1.0f / lrow[0], 1.0f / lrow[1]};

    float* Ob = Og + (size_t)b * 16384;
    #pragma unroll
    for (int dt = 0; dt < 8; ++dt) {
        const int colo = dt * 8 + cp * 2;
        *(float2*)(Ob + (size_t)r0 * 64 + colo) =
            make_float2(oa[dt][0] * corr[0], oa[dt][1] * corr[0]);
        *(float2*)(Ob + (size_t)(r0 + 8) * 64 + colo) =
            make_float2(oa[dt][2] * corr[1], oa[dt][3] * corr[1]);
    }
}

} // namespace

extern "C" void kernel_launch(void* const* d_in, const int* in_sizes, int n_in,
                              void* d_out, int out_size)
{
    const float* Q = (const float*)d_in[0];
    const float* K = (const float*)d_in[1];
    const float* V = (const float*)d_in[2];
    const int*   L = (const int*)  d_in[3];
    const float* W = (const float*)d_in[4];
    float*       O = (float*)d_out;

    const int n = in_sizes[0] / (256 * 64);   // 2048 batches

    cudaFuncSetAttribute(attn_mma, cudaFuncAttributeMaxDynamicSharedMemorySize, SMEM_BYTES);
    attn_mma<<<n, 512, SMEM_BYTES>>>(Q, K, V, L, W, O);
}